// round 5
// baseline (speedup 1.0000x reference)
#include <cuda_runtime.h>
#include <math.h>

// L=3,B=16,K=8,N=256,D=768,M=2048,H=128,MID=64,g=16,IMG=240. Output float32 concat:
#define OFF_RES   0ull
#define OFF_SCORE 12288ull
#define OFF_PLOG  24576ull
#define OFF_GLOG  36864ull
#define OFF_LOCAL 36912ull
#define OFF_PW    5566512ull
#define OFF_IDX   5566518ull
#define OFF_ALN   5578806ull

__device__ float g_qn   [3*16*256*768];
__device__ float g_pinv [3*16*2048];
__device__ float g_pmaxv[3*16*256*2];
__device__ int   g_pmaxi[3*16*256*2];
__device__ float g_cmap [3*16*768*256];
__device__ float g_gap  [3*16*768];
__device__ float g_gmp  [3*16*768];
__device__ float g_w1t  [3*6912*128];
__device__ float g_w2t  [3*1152*64];
__device__ float g_wt1t [3*4*128*128];
__device__ float g_wt2t [3*4*64*64];
__device__ float g_x1   [3*16*128*256];
__device__ float g_x2   [3*16*128*1024];
__device__ float g_x3   [3*16*64*1024];
__device__ float g_x4   [3*16*64*4096];
__device__ float g_raw  [3*16*2*4096];

// ---- weight transposes (all four in one kernel) ----
__global__ void k_tw(const float* __restrict__ lw1, const float* __restrict__ lw2,
                     const float* __restrict__ lwt1, const float* __restrict__ lwt2){
    int idx = blockIdx.x*256 + threadIdx.x;
    if(idx < 3*6912*128){
        int o=idx&127, kk=(idx>>7)%6912, l=idx/(6912*128);
        g_w1t[idx] = lw1[((size_t)(l*128+o)*768 + kk%768)*9 + kk/768];
    } else if((idx -= 3*6912*128) < 3*1152*64){
        int o=idx&63, kk=(idx>>6)%1152, l=idx/(1152*64);
        g_w2t[idx] = lw2[((size_t)(l*64+o)*128 + kk%128)*9 + kk/128];
    } else if((idx -= 3*1152*64) < 3*4*128*128){
        int o=idx&127, c=(idx>>7)&127, pq=(idx>>14)&3, l=idx>>16;
        g_wt1t[idx] = lwt1[((size_t)(l*128+c)*128+o)*4+pq];
    } else if((idx -= 3*4*128*128) < 3*4*64*64){
        int o=idx&63, c=(idx>>6)&63, pq=(idx>>12)&3, l=idx>>14;
        g_wt2t[idx] = lwt2[((size_t)(l*64+c)*64+o)*4+pq];
    }
}

// ---- row norms ----
__global__ void k_norm_q(const float* __restrict__ q){
    int row = blockIdx.x*8 + (threadIdx.x>>5), lane = threadIdx.x&31;
    const float* src = q + (size_t)row*768;
    float v[24]; float ss = 0.f;
    #pragma unroll
    for(int i=0;i<24;i++){ v[i]=src[lane+i*32]; ss += v[i]*v[i]; }
    #pragma unroll
    for(int o=16;o;o>>=1) ss += __shfl_xor_sync(~0u, ss, o);
    float inv = 1.f/fmaxf(sqrtf(ss),1e-12f);
    float* dst = g_qn + (size_t)row*768;
    #pragma unroll
    for(int i=0;i<24;i++) dst[lane+i*32] = v[i]*inv;
}
__global__ void k_norm_p(const float* __restrict__ prompt){
    int row = blockIdx.x*8 + (threadIdx.x>>5), lane = threadIdx.x&31;
    const float* src = prompt + (size_t)row*768;
    float ss = 0.f;
    #pragma unroll
    for(int i=0;i<24;i++){ float x=src[lane+i*32]; ss += x*x; }
    #pragma unroll
    for(int o=16;o;o>>=1) ss += __shfl_xor_sync(~0u, ss, o);
    if(!lane) g_pinv[row] = 1.f/fmaxf(sqrtf(ss),1e-12f);
}

// ---- cosine GEMM + fused max/argmax. grid 384 = lb48 * nt4 * ms2 ----
__global__ __launch_bounds__(256) void k_sim(const float* __restrict__ prompt){
    int bid = blockIdx.x, ms = bid&1, nt = (bid>>1)&3, lb = bid>>3;
    int tid = threadIdx.x, tx = tid&15, ty = tid>>4;
    __shared__ float sA[16][68];
    __shared__ float sB[16][132];
    const float* A = g_qn + ((size_t)lb*256 + nt*64)*768;
    const float* P = prompt + (size_t)lb*2048*768;
    const float* pinv = g_pinv + lb*2048;
    int rA = tid>>2, kq = tid&3;
    const float* pa = A + (size_t)rA*768 + kq*4;
    int rB0 = tid>>2, rB1 = 64 + rB0;
    float bestv[4]; int besti[4];
    #pragma unroll
    for(int i=0;i<4;i++){ bestv[i]=-2.f; besti[i]=0; }
    for(int mt=0; mt<8; mt++){
        int m0 = (ms*8+mt)*128;
        const float* pb0 = P + (size_t)(m0+rB0)*768 + kq*4;
        const float* pb1 = P + (size_t)(m0+rB1)*768 + kq*4;
        float sc0 = pinv[m0+rB0], sc1 = pinv[m0+rB1];
        float acc[4][8];
        #pragma unroll
        for(int i=0;i<4;i++)
            #pragma unroll
            for(int j=0;j<8;j++) acc[i][j]=0.f;
        for(int kc=0; kc<48; kc++){
            float4 a4 = *(const float4*)(pa + kc*16);
            float4 b4 = *(const float4*)(pb0 + kc*16);
            float4 c4 = *(const float4*)(pb1 + kc*16);
            sA[kq*4+0][rA]=a4.x; sA[kq*4+1][rA]=a4.y; sA[kq*4+2][rA]=a4.z; sA[kq*4+3][rA]=a4.w;
            sB[kq*4+0][rB0]=b4.x*sc0; sB[kq*4+1][rB0]=b4.y*sc0; sB[kq*4+2][rB0]=b4.z*sc0; sB[kq*4+3][rB0]=b4.w*sc0;
            sB[kq*4+0][rB1]=c4.x*sc1; sB[kq*4+1][rB1]=c4.y*sc1; sB[kq*4+2][rB1]=c4.z*sc1; sB[kq*4+3][rB1]=c4.w*sc1;
            __syncthreads();
            #pragma unroll
            for(int k=0;k<16;k++){
                float4 a  = *(const float4*)&sA[k][ty*4];
                float4 b0 = *(const float4*)&sB[k][tx*4];
                float4 b1 = *(const float4*)&sB[k][64+tx*4];
                float av[4]={a.x,a.y,a.z,a.w};
                float bv[8]={b0.x,b0.y,b0.z,b0.w,b1.x,b1.y,b1.z,b1.w};
                #pragma unroll
                for(int i=0;i<4;i++)
                    #pragma unroll
                    for(int j=0;j<8;j++) acc[i][j]=fmaf(av[i],bv[j],acc[i][j]);
            }
            __syncthreads();
        }
        #pragma unroll
        for(int i=0;i<4;i++)
            #pragma unroll
            for(int j=0;j<8;j++){
                int cidx = m0 + ((j<4)? tx*4+j : 64+tx*4+(j-4));
                if(acc[i][j] > bestv[i]){ bestv[i]=acc[i][j]; besti[i]=cidx; }
            }
    }
    #pragma unroll
    for(int off=1; off<16; off<<=1)
        #pragma unroll
        for(int i=0;i<4;i++){
            float ov = __shfl_xor_sync(~0u, bestv[i], off);
            int   oi = __shfl_xor_sync(~0u, besti[i], off);
            if(ov>bestv[i] || (ov==bestv[i] && oi<besti[i])){ bestv[i]=ov; besti[i]=oi; }
        }
    if(!tx)
        #pragma unroll
        for(int i=0;i<4;i++){
            int n = nt*64 + ty*4 + i;
            int gdst = (lb*256+n)*2 + ms;
            g_pmaxv[gdst]=bestv[i]; g_pmaxi[gdst]=besti[i];
        }
}

// ---- combine argmax halves, gather aligned, build ctx map ----
__global__ void k_ctx(const float* __restrict__ prompt, float* __restrict__ out){
    int gid = blockIdx.x, lb = gid>>8, n = gid&255, tid = threadIdx.x;
    __shared__ float red[256];
    __shared__ int   smi;
    __shared__ float sinv;
    if(!tid){
        float v0=g_pmaxv[gid*2], v1=g_pmaxv[gid*2+1];
        int i0=g_pmaxi[gid*2], i1=g_pmaxi[gid*2+1];
        float v; int mi;
        if(v0>v1 || (v0==v1 && i0<i1)){ v=v0; mi=i0; } else { v=v1; mi=i1; }
        out[OFF_RES+gid] = 0.5f*(1.f-v);
        out[OFF_IDX+gid] = (float)mi;
        smi = mi;
    }
    __syncthreads();
    const float* pr = prompt + (size_t)lb*2048*768 + (size_t)smi*768;
    float vloc[3]; float ss=0.f;
    #pragma unroll
    for(int i=0;i<3;i++){ float x=pr[tid+i*256]; vloc[i]=x; ss+=x*x; }
    red[tid]=ss; __syncthreads();
    for(int s=128;s;s>>=1){ if(tid<s) red[tid]+=red[tid+s]; __syncthreads(); }
    if(!tid) sinv = 1.f/fmaxf(sqrtf(red[0]),1e-12f);
    __syncthreads();
    float ainv = sinv;
    #pragma unroll
    for(int i=0;i<3;i++){
        int d = tid + i*256;
        float qv = g_qn[(size_t)gid*768 + d];
        float an = vloc[i]*ainv;
        g_cmap[((size_t)lb*768+d)*256 + n] = qv + fabsf(qv - an);
        out[OFF_ALN + (size_t)gid*768 + d] = vloc[i];
    }
}

// ---- generic training-mode BatchNorm2d (which: 0=cmap,1=x1+relu,2=x3+relu) ----
__global__ void k_bn(int which, const float* __restrict__ gg, const float* __restrict__ bb,
                     int C, int HW, int relu){
    float* x = which==0 ? g_cmap : which==1 ? g_x1 : g_x3;
    int l = blockIdx.x / C, c = blockIdx.x % C, tid = threadIdx.x;
    int per = HW >> 8;
    double s=0.0, s2=0.0;
    for(int b=0;b<16;b++)
        for(int i=0;i<per;i++){
            float v = x[(((size_t)(l*16+b))*C + c)*HW + i*256 + tid];
            s += v; s2 += (double)v*v;
        }
    __shared__ double rs[256], rs2[256];
    rs[tid]=s; rs2[tid]=s2; __syncthreads();
    for(int st=128;st;st>>=1){ if(tid<st){rs[tid]+=rs[tid+st]; rs2[tid]+=rs2[tid+st];} __syncthreads(); }
    __shared__ float sc, sh;
    if(!tid){
        double cnt = 16.0*HW, m = rs[0]/cnt, var = rs2[0]/cnt - m*m;
        float scale = gg[l*C+c]*rsqrtf((float)var + 1e-5f);
        sc = scale; sh = bb[l*C+c] - (float)m*scale;
    }
    __syncthreads();
    for(int b=0;b<16;b++)
        for(int i=0;i<per;i++){
            size_t a = (((size_t)(l*16+b))*C + c)*HW + i*256 + tid;
            float v = x[a]*sc + sh;
            x[a] = relu ? fmaxf(v,0.f) : v;
        }
}

// ---- GAP / GMP over post-BN cmap ----
__global__ void k_gapmax(){
    int lb = blockIdx.x/96, dc = blockIdx.x%96;
    int w = threadIdx.x>>5, lane = threadIdx.x&31;
    int d = dc*8 + w;
    const float* p = g_cmap + ((size_t)lb*768+d)*256;
    float s=0.f, mx=-3.4e38f;
    #pragma unroll
    for(int i=0;i<8;i++){ float x=p[lane+i*32]; s+=x; mx=fmaxf(mx,x); }
    #pragma unroll
    for(int o=16;o;o>>=1){ s += __shfl_xor_sync(~0u,s,o); mx = fmaxf(mx,__shfl_xor_sync(~0u,mx,o)); }
    if(!lane){ g_gap[lb*768+d]=s*(1.f/256.f); g_gmp[lb*768+d]=mx; }
}

// ---- conv1 3x3 768->128 @16x16 (implicit GEMM). grid 192 = lb48*pt4 ----
__global__ __launch_bounds__(256) void k_conv1(){
    int bid = blockIdx.x, pt = bid&3, lb = bid>>2, l = lb>>4;
    int tid = threadIdx.x, tx = tid&15, ty = tid>>4;
    __shared__ float sA[16][132];
    __shared__ float sB[16][68];
    const float* W = g_w1t + (size_t)l*6912*128;
    const float* X = g_cmap + (size_t)lb*768*256;
    int p0 = pt*64;
    float acc[8][4];
    #pragma unroll
    for(int i=0;i<8;i++)
        #pragma unroll
        for(int j=0;j<4;j++) acc[i][j]=0.f;
    for(int kc=0; kc<432; kc++){
        int rs = kc/48, c0 = (kc%48)*16;
        int r = rs/3-1, s = rs%3-1;
        #pragma unroll
        for(int qq=0;qq<2;qq++){
            int e = tid + qq*256, o4 = e&31, k = e>>5;
            *(float4*)&sA[k][o4*4] = *(const float4*)(W + ((size_t)(kc*16+k))*128 + o4*4);
        }
        #pragma unroll
        for(int qq=0;qq<4;qq++){
            int e = tid + qq*256, k = e>>6, p = e&63;
            int pg = p0+p, y = (pg>>4)+r, x = (pg&15)+s;
            float v = 0.f;
            if((unsigned)y<16u && (unsigned)x<16u) v = X[((size_t)(c0+k))*256 + y*16 + x];
            sB[k][p] = v;
        }
        __syncthreads();
        #pragma unroll
        for(int k=0;k<16;k++){
            float4 a0 = *(const float4*)&sA[k][ty*4];
            float4 a1 = *(const float4*)&sA[k][64+ty*4];
            float4 b  = *(const float4*)&sB[k][tx*4];
            float av[8]={a0.x,a0.y,a0.z,a0.w,a1.x,a1.y,a1.z,a1.w};
            float bv[4]={b.x,b.y,b.z,b.w};
            #pragma unroll
            for(int i=0;i<8;i++)
                #pragma unroll
                for(int j=0;j<4;j++) acc[i][j]=fmaf(av[i],bv[j],acc[i][j]);
        }
        __syncthreads();
    }
    float* Y = g_x1 + (size_t)lb*128*256;
    #pragma unroll
    for(int i=0;i<8;i++){
        int o = (i<4)? ty*4+i : 64+ty*4+(i-4);
        #pragma unroll
        for(int j=0;j<4;j++) Y[(size_t)o*256 + p0 + tx*4 + j] = acc[i][j];
    }
}

// ---- convT1 2x2 s2 128->128. grid 768 = lb48*pq4*pt4 ----
__global__ __launch_bounds__(256) void k_convT1(const float* __restrict__ bt1){
    int bid = blockIdx.x, pt = bid&3, pq = (bid>>2)&3, lb = bid>>4, l = lb>>4;
    int p = pq>>1, qd = pq&1;
    int tid = threadIdx.x, tx = tid&15, ty = tid>>4;
    __shared__ float sA[16][132];
    __shared__ float sB[16][68];
    const float* W = g_wt1t + (size_t)(l*4+pq)*128*128;
    const float* X = g_x1 + (size_t)lb*128*256;
    int p0 = pt*64;
    float acc[8][4];
    #pragma unroll
    for(int i=0;i<8;i++)
        #pragma unroll
        for(int j=0;j<4;j++) acc[i][j]=0.f;
    for(int kc=0; kc<8; kc++){
        #pragma unroll
        for(int qq=0;qq<2;qq++){
            int e = tid + qq*256, o4 = e&31, k = e>>5;
            *(float4*)&sA[k][o4*4] = *(const float4*)(W + ((size_t)(kc*16+k))*128 + o4*4);
        }
        { int p4 = tid&15, k = tid>>4;
          *(float4*)&sB[k][p4*4] = *(const float4*)(X + ((size_t)(kc*16+k))*256 + p0 + p4*4); }
        __syncthreads();
        #pragma unroll
        for(int k=0;k<16;k++){
            float4 a0 = *(const float4*)&sA[k][ty*4];
            float4 a1 = *(const float4*)&sA[k][64+ty*4];
            float4 b  = *(const float4*)&sB[k][tx*4];
            float av[8]={a0.x,a0.y,a0.z,a0.w,a1.x,a1.y,a1.z,a1.w};
            float bv[4]={b.x,b.y,b.z,b.w};
            #pragma unroll
            for(int i=0;i<8;i++)
                #pragma unroll
                for(int j=0;j<4;j++) acc[i][j]=fmaf(av[i],bv[j],acc[i][j]);
        }
        __syncthreads();
    }
    float* Y = g_x2 + (size_t)lb*128*1024;
    #pragma unroll
    for(int i=0;i<8;i++){
        int o = (i<4)? ty*4+i : 64+ty*4+(i-4);
        float bias = bt1[l*128+o];
        #pragma unroll
        for(int j=0;j<4;j++){
            int hw = p0 + tx*4 + j, h = hw>>4, w = hw&15;
            Y[(size_t)o*1024 + (2*h+p)*32 + 2*w + qd] = acc[i][j] + bias;
        }
    }
}

// ---- conv2 3x3 128->64 @32x32. grid 384 = lb48*pt8 ----
__global__ __launch_bounds__(256) void k_conv2(){
    int bid = blockIdx.x, pt = bid&7, lb = bid>>3, l = lb>>4;
    int tid = threadIdx.x, tx = tid&15, ty = tid>>4;
    __shared__ float sA[16][68];
    __shared__ float sB[16][132];
    const float* W = g_w2t + (size_t)l*1152*64;
    const float* X = g_x2 + (size_t)lb*128*1024;
    int p0 = pt*128;
    float acc[4][8];
    #pragma unroll
    for(int i=0;i<4;i++)
        #pragma unroll
        for(int j=0;j<8;j++) acc[i][j]=0.f;
    for(int kc=0; kc<72; kc++){
        int rs = kc>>3, c0 = (kc&7)*16;
        int r = rs/3-1, s = rs%3-1;
        { int o4 = tid&15, k = tid>>4;
          *(float4*)&sA[k][o4*4] = *(const float4*)(W + ((size_t)(kc*16+k))*64 + o4*4); }
        #pragma unroll
        for(int qq=0;qq<8;qq++){
            int e = tid + qq*256, k = e>>7, p = e&127;
            int pg = p0+p, y = (pg>>5)+r, x = (pg&31)+s;
            float v = 0.f;
            if((unsigned)y<32u && (unsigned)x<32u) v = X[((size_t)(c0+k))*1024 + y*32 + x];
            sB[k][p] = v;
        }
        __syncthreads();
        #pragma unroll
        for(int k=0;k<16;k++){
            float4 a  = *(const float4*)&sA[k][ty*4];
            float4 b0 = *(const float4*)&sB[k][tx*4];
            float4 b1 = *(const float4*)&sB[k][64+tx*4];
            float av[4]={a.x,a.y,a.z,a.w};
            float bv[8]={b0.x,b0.y,b0.z,b0.w,b1.x,b1.y,b1.z,b1.w};
            #pragma unroll
            for(int i=0;i<4;i++)
                #pragma unroll
                for(int j=0;j<8;j++) acc[i][j]=fmaf(av[i],bv[j],acc[i][j]);
        }
        __syncthreads();
    }
    float* Y = g_x3 + (size_t)lb*64*1024;
    #pragma unroll
    for(int i=0;i<4;i++){
        int o = ty*4+i;
        #pragma unroll
        for(int j=0;j<8;j++){
            int pix = p0 + ((j<4)? tx*4+j : 64+tx*4+(j-4));
            Y[(size_t)o*1024 + pix] = acc[i][j];
        }
    }
}

// ---- convT2 2x2 s2 64->64. grid 1536 = lb48*pq4*pt8 ----
__global__ __launch_bounds__(256) void k_convT2(const float* __restrict__ bt2){
    int bid = blockIdx.x, pt = bid&7, pq = (bid>>3)&3, lb = bid>>5, l = lb>>4;
    int p = pq>>1, qd = pq&1;
    int tid = threadIdx.x, tx = tid&15, ty = tid>>4;
    __shared__ float sA[16][68];
    __shared__ float sB[16][132];
    const float* W = g_wt2t + (size_t)(l*4+pq)*64*64;
    const float* X = g_x3 + (size_t)lb*64*1024;
    int p0 = pt*128;
    float acc[4][8];
    #pragma unroll
    for(int i=0;i<4;i++)
        #pragma unroll
        for(int j=0;j<8;j++) acc[i][j]=0.f;
    for(int kc=0; kc<4; kc++){
        { int o4 = tid&15, k = tid>>4;
          *(float4*)&sA[k][o4*4] = *(const float4*)(W + ((size_t)(kc*16+k))*64 + o4*4); }
        #pragma unroll
        for(int qq=0;qq<2;qq++){
            int e = tid + qq*256, p4 = e&31, k = e>>5;
            *(float4*)&sB[k][p4*4] = *(const float4*)(X + ((size_t)(kc*16+k))*1024 + p0 + p4*4);
        }
        __syncthreads();
        #pragma unroll
        for(int k=0;k<16;k++){
            float4 a  = *(const float4*)&sA[k][ty*4];
            float4 b0 = *(const float4*)&sB[k][tx*4];
            float4 b1 = *(const float4*)&sB[k][64+tx*4];
            float av[4]={a.x,a.y,a.z,a.w};
            float bv[8]={b0.x,b0.y,b0.z,b0.w,b1.x,b1.y,b1.z,b1.w};
            #pragma unroll
            for(int i=0;i<4;i++)
                #pragma unroll
                for(int j=0;j<8;j++) acc[i][j]=fmaf(av[i],bv[j],acc[i][j]);
        }
        __syncthreads();
    }
    float* Y = g_x4 + (size_t)lb*64*4096;
    #pragma unroll
    for(int i=0;i<4;i++){
        int o = ty*4+i;
        float bias = bt2[l*64+o];
        #pragma unroll
        for(int j=0;j<8;j++){
            int hw = p0 + ((j<4)? tx*4+j : 64+tx*4+(j-4));
            int h = hw>>5, w = hw&31;
            Y[(size_t)o*4096 + (2*h+p)*64 + 2*w + qd] = acc[i][j] + bias;
        }
    }
}

// ---- conv3 1x1 64->2 ----
__global__ void k_conv3(const float* __restrict__ lw3, const float* __restrict__ lb3){
    int lb = blockIdx.x, l = lb>>4, tid = threadIdx.x;
    __shared__ float w[2][64];
    if(tid<128) w[tid>>6][tid&63] = lw3[l*128 + tid];
    __syncthreads();
    float b0 = lb3[l*2], b1 = lb3[l*2+1];
    const float* X = g_x4 + (size_t)lb*64*4096;
    float* R = g_raw + (size_t)lb*2*4096;
    for(int i=0;i<16;i++){
        int pix = tid + i*256;
        float a0=b0, a1=b1;
        #pragma unroll 8
        for(int c=0;c<64;c++){
            float v = X[(size_t)c*4096 + pix];
            a0 = fmaf(v, w[0][c], a0); a1 = fmaf(v, w[1][c], a1);
        }
        R[pix]=a0; R[4096+pix]=a1;
    }
}

// ---- adaptive pool 64->16 + patch outputs ----
__global__ void k_pool(float* __restrict__ out){
    int lb = blockIdx.x, tid = threadIdx.x;
    int py = tid>>4, px = tid&15;
    const float* R = g_raw + (size_t)lb*2*4096;
    float s0=0.f, s1=0.f;
    #pragma unroll
    for(int dy=0;dy<4;dy++)
        #pragma unroll
        for(int dx=0;dx<4;dx++){
            int a = (py*4+dy)*64 + px*4+dx;
            s0 += R[a]; s1 += R[4096+a];
        }
    s0 *= 0.0625f; s1 *= 0.0625f;
    float d = s1 - s0;
    out[OFF_PLOG + lb*256 + tid] = d;
    out[OFF_SCORE + lb*256 + tid] = 1.f/(1.f + expf(-d));
}

// ---- bilinear resize 64->240 ----
__global__ void k_resize(float* __restrict__ out){
    int idx = blockIdx.x*256 + threadIdx.x;
    if(idx >= 3*16*2*240*240) return;
    int x = idx%240, y = (idx/240)%240, m = idx/57600;
    const float* R = g_raw + (size_t)m*4096;
    float sy = (y+0.5f)*(64.f/240.f) - 0.5f;
    float sx = (x+0.5f)*(64.f/240.f) - 0.5f;
    int y0 = (int)floorf(sy); float fy = sy - y0;
    int x0 = (int)floorf(sx); float fx = sx - x0;
    int ya = max(y0,0), yb = min(y0+1,63), xa = max(x0,0), xb = min(x0+1,63);
    float v = (1.f-fy)*((1.f-fx)*R[ya*64+xa] + fx*R[ya*64+xb])
            +      fy *((1.f-fx)*R[yb*64+xa] + fx*R[yb*64+xb]);
    out[OFF_LOCAL + idx] = v;
}

// ---- global head: pooled -> linear -> LN -> relu -> linear -> glogit; pw out ----
__global__ void k_head(const float* __restrict__ pool_logits, const float* __restrict__ mw1,
                       const float* __restrict__ mlng, const float* __restrict__ mlnb,
                       const float* __restrict__ mw2, const float* __restrict__ mb2,
                       float* __restrict__ out){
    int lb = blockIdx.x, l = lb>>4, tid = threadIdx.x;
    float pl0 = pool_logits[l*2], pl1 = pool_logits[l*2+1];
    float mx = fmaxf(pl0,pl1);
    float e0 = expf(pl0-mx), e1 = expf(pl1-mx);
    float pw0 = e0/(e0+e1), pw1 = e1/(e0+e1);
    if((lb&15)==0 && tid<2) out[OFF_PW + l*2 + tid] = tid ? pw1 : pw0;
    const float* gp = g_gap + (size_t)lb*768;
    const float* gm = g_gmp + (size_t)lb*768;
    const float* W = mw1 + (size_t)(l*128+tid)*768;
    float acc = 0.f;
    for(int d=0; d<768; d++) acc = fmaf(pw0*gp[d] + pw1*gm[d], W[d], acc);
    __shared__ double rd[128];
    rd[tid] = acc; __syncthreads();
    for(int s=64;s;s>>=1){ if(tid<s) rd[tid]+=rd[tid+s]; __syncthreads(); }
    __shared__ float smean;
    if(!tid) smean = (float)(rd[0]/128.0);
    __syncthreads();
    float m = smean, dx = acc - m;
    rd[tid] = (double)dx*dx; __syncthreads();
    for(int s=64;s;s>>=1){ if(tid<s) rd[tid]+=rd[tid+s]; __syncthreads(); }
    __shared__ float svar;
    if(!tid) svar = (float)(rd[0]/128.0);
    __syncthreads();
    float h = fmaxf(mlng[l*128+tid]*dx*rsqrtf(svar+1e-5f) + mlnb[l*128+tid], 0.f);
    rd[tid] = (double)h*mw2[l*256+tid]; __syncthreads();
    for(int s=64;s;s>>=1){ if(tid<s) rd[tid]+=rd[tid+s]; __syncthreads(); }
    __shared__ float sl0;
    if(!tid) sl0 = (float)rd[0];
    __syncthreads();
    rd[tid] = (double)h*mw2[l*256+128+tid]; __syncthreads();
    for(int s=64;s;s>>=1){ if(tid<s) rd[tid]+=rd[tid+s]; __syncthreads(); }
    if(!tid){
        float l1v = (float)rd[0] + mb2[l*2+1];
        float l0v = sl0 + mb2[l*2];
        out[OFF_GLOG + lb] = l1v - l0v;
    }
}

extern "C" void kernel_launch(void* const* d_in, const int* in_sizes, int n_in,
                              void* d_out, int out_size){
    const float* query   = (const float*)d_in[0];
    const float* prompt  = (const float*)d_in[1];
    const float* sbg     = (const float*)d_in[2];
    const float* sbb     = (const float*)d_in[3];
    const float* lw1     = (const float*)d_in[4];
    const float* lbn1g   = (const float*)d_in[5];
    const float* lbn1b   = (const float*)d_in[6];
    const float* lwt1    = (const float*)d_in[7];
    const float* lbt1    = (const float*)d_in[8];
    const float* lw2     = (const float*)d_in[9];
    const float* lbn2g   = (const float*)d_in[10];
    const float* lbn2b   = (const float*)d_in[11];
    const float* lwt2    = (const float*)d_in[12];
    const float* lbt2    = (const float*)d_in[13];
    const float* lw3     = (const float*)d_in[14];
    const float* lb3     = (const float*)d_in[15];
    const float* plog    = (const float*)d_in[16];
    const float* mw1     = (const float*)d_in[17];
    const float* mlng    = (const float*)d_in[18];
    const float* mlnb    = (const float*)d_in[19];
    const float* mw2     = (const float*)d_in[20];
    const float* mb2     = (const float*)d_in[21];
    float* out = (float*)d_out;

    k_tw<<<12192,256>>>(lw1, lw2, lwt1, lwt2);
    k_norm_q<<<1536,256>>>(query);
    k_norm_p<<<12288,256>>>(prompt);
    k_sim<<<384,256>>>(prompt);
    k_ctx<<<12288,256>>>(prompt, out);
    k_bn<<<3*768,256>>>(0, sbg, sbb, 768, 256, 0);
    k_gapmax<<<4608,256>>>();
    k_conv1<<<192,256>>>();
    k_bn<<<3*128,256>>>(1, lbn1g, lbn1b, 128, 256, 1);
    k_convT1<<<768,256>>>(lbt1);
    k_conv2<<<384,256>>>();
    k_bn<<<3*64,256>>>(2, lbn2g, lbn2b, 64, 1024, 1);
    k_convT2<<<1536,256>>>(lbt2);
    k_conv3<<<48,256>>>(lw3, lb3);
    k_pool<<<48,256>>>(out);
    k_resize<<<21600,256>>>(out);
    k_head<<<48,128>>>(plog, mw1, mlng, mlnb, mw2, mb2, out);
}

// round 6
// speedup vs baseline: 1.1940x; 1.1940x over previous
#include <cuda_runtime.h>
#include <math.h>

// L=3,B=16,K=8,N=256,D=768,M=2048,H=128,MID=64,g=16,IMG=240. Output float32 concat:
#define OFF_RES   0ull
#define OFF_SCORE 12288ull
#define OFF_PLOG  24576ull
#define OFF_GLOG  36864ull
#define OFF_LOCAL 36912ull
#define OFF_PW    5566512ull
#define OFF_IDX   5566518ull
#define OFF_ALN   5578806ull

__device__ float g_qn   [3*16*256*768];
__device__ float g_pinv [3*16*2048];
__device__ float g_pmaxv[3*16*256*3];
__device__ int   g_pmaxi[3*16*256*3];
__device__ float g_cmap [3*16*768*256];
__device__ float g_gap  [3*16*768];
__device__ float g_gmp  [3*16*768];
__device__ float g_w1t  [3*6912*128];
__device__ float g_w2t  [3*1152*64];
__device__ float g_wt1t [3*4*128*128];
__device__ float g_wt2t [3*4*64*64];
__device__ float g_x1   [3*16*128*256];
__device__ float g_x1b  [3*16*128*256];
__device__ float g_x1c  [3*16*128*256];
__device__ float g_x2   [3*16*128*1024];
__device__ float g_x3   [3*16*64*1024];
__device__ float g_x4   [3*16*64*4096];
__device__ float g_raw  [3*16*2*4096];

// ---- weight transposes ----
__global__ void k_tw(const float* __restrict__ lw1, const float* __restrict__ lw2,
                     const float* __restrict__ lwt1, const float* __restrict__ lwt2){
    int idx = blockIdx.x*256 + threadIdx.x;
    if(idx < 3*6912*128){
        int o=idx&127, kk=(idx>>7)%6912, l=idx/(6912*128);
        g_w1t[idx] = lw1[((size_t)(l*128+o)*768 + kk%768)*9 + kk/768];
    } else if((idx -= 3*6912*128) < 3*1152*64){
        int o=idx&63, kk=(idx>>6)%1152, l=idx/(1152*64);
        g_w2t[idx] = lw2[((size_t)(l*64+o)*128 + kk%128)*9 + kk/128];
    } else if((idx -= 3*1152*64) < 3*4*128*128){
        int o=idx&127, c=(idx>>7)&127, pq=(idx>>14)&3, l=idx>>16;
        g_wt1t[idx] = lwt1[((size_t)(l*128+c)*128+o)*4+pq];
    } else if((idx -= 3*4*128*128) < 3*4*64*64){
        int o=idx&63, c=(idx>>6)&63, pq=(idx>>12)&3, l=idx>>14;
        g_wt2t[idx] = lwt2[((size_t)(l*64+c)*64+o)*4+pq];
    }
}

// ---- row norms ----
__global__ void k_norm_q(const float* __restrict__ q){
    int row = blockIdx.x*8 + (threadIdx.x>>5), lane = threadIdx.x&31;
    const float* src = q + (size_t)row*768;
    float v[24]; float ss = 0.f;
    #pragma unroll
    for(int i=0;i<24;i++){ v[i]=src[lane+i*32]; ss += v[i]*v[i]; }
    #pragma unroll
    for(int o=16;o;o>>=1) ss += __shfl_xor_sync(~0u, ss, o);
    float inv = 1.f/fmaxf(sqrtf(ss),1e-12f);
    float* dst = g_qn + (size_t)row*768;
    #pragma unroll
    for(int i=0;i<24;i++) dst[lane+i*32] = v[i]*inv;
}
__global__ void k_norm_p(const float* __restrict__ prompt){
    int row = blockIdx.x*8 + (threadIdx.x>>5), lane = threadIdx.x&31;
    const float* src = prompt + (size_t)row*768;
    float ss = 0.f;
    #pragma unroll
    for(int i=0;i<24;i++){ float x=src[lane+i*32]; ss += x*x; }
    #pragma unroll
    for(int o=16;o;o>>=1) ss += __shfl_xor_sync(~0u, ss, o);
    if(!lane) g_pinv[row] = 1.f/fmaxf(sqrtf(ss),1e-12f);
}

// ---- cosine GEMM + fused max/argmax. 128x128 tiles, 8x8 micro. grid 288 = lb48*nt2*ms3 ----
__global__ __launch_bounds__(256,2) void k_sim(const float* __restrict__ prompt){
    int bid = blockIdx.x;
    int ms = bid%3, nt = (bid/3)&1, lb = bid/6;
    int tid = threadIdx.x, tx = tid&15, ty = tid>>4;
    __shared__ float sA[16][132];
    __shared__ float sB[16][132];
    const float* A = g_qn + ((size_t)lb*256 + nt*128)*768;
    const float* P = prompt + (size_t)lb*2048*768;
    const float* pinv = g_pinv + lb*2048;
    int r0 = tid>>2, r1 = 64 + r0, kq = tid&3;
    const float* pa0 = A + (size_t)r0*768 + kq*4;
    const float* pa1 = A + (size_t)r1*768 + kq*4;
    int mt0  = (ms==0) ? 0 : (ms*5+1);
    int mcnt = (ms==0) ? 6 : 5;
    float bestv[8]; int besti[8];
    #pragma unroll
    for(int i=0;i<8;i++){ bestv[i]=-2.f; besti[i]=0; }
    for(int mtl=0; mtl<mcnt; mtl++){
        int m0 = (mt0+mtl)*128;
        const float* pb0 = P + (size_t)(m0+r0)*768 + kq*4;
        const float* pb1 = P + (size_t)(m0+r1)*768 + kq*4;
        float sc0 = pinv[m0+r0], sc1 = pinv[m0+r1];
        float acc[8][8];
        #pragma unroll
        for(int i=0;i<8;i++)
            #pragma unroll
            for(int j=0;j<8;j++) acc[i][j]=0.f;
        for(int kc=0; kc<48; kc++){
            float4 a0 = *(const float4*)(pa0 + kc*16);
            float4 a1 = *(const float4*)(pa1 + kc*16);
            float4 b0 = *(const float4*)(pb0 + kc*16);
            float4 b1 = *(const float4*)(pb1 + kc*16);
            sA[kq*4+0][r0]=a0.x; sA[kq*4+1][r0]=a0.y; sA[kq*4+2][r0]=a0.z; sA[kq*4+3][r0]=a0.w;
            sA[kq*4+0][r1]=a1.x; sA[kq*4+1][r1]=a1.y; sA[kq*4+2][r1]=a1.z; sA[kq*4+3][r1]=a1.w;
            sB[kq*4+0][r0]=b0.x*sc0; sB[kq*4+1][r0]=b0.y*sc0; sB[kq*4+2][r0]=b0.z*sc0; sB[kq*4+3][r0]=b0.w*sc0;
            sB[kq*4+0][r1]=b1.x*sc1; sB[kq*4+1][r1]=b1.y*sc1; sB[kq*4+2][r1]=b1.z*sc1; sB[kq*4+3][r1]=b1.w*sc1;
            __syncthreads();
            #pragma unroll
            for(int k=0;k<16;k++){
                float4 av0 = *(const float4*)&sA[k][ty*4];
                float4 av1 = *(const float4*)&sA[k][64+ty*4];
                float4 bv0 = *(const float4*)&sB[k][tx*4];
                float4 bv1 = *(const float4*)&sB[k][64+tx*4];
                float av[8]={av0.x,av0.y,av0.z,av0.w,av1.x,av1.y,av1.z,av1.w};
                float bv[8]={bv0.x,bv0.y,bv0.z,bv0.w,bv1.x,bv1.y,bv1.z,bv1.w};
                #pragma unroll
                for(int i=0;i<8;i++)
                    #pragma unroll
                    for(int j=0;j<8;j++) acc[i][j]=fmaf(av[i],bv[j],acc[i][j]);
            }
            __syncthreads();
        }
        #pragma unroll
        for(int i=0;i<8;i++)
            #pragma unroll
            for(int j=0;j<8;j++){
                int cidx = m0 + ((j<4)? tx*4+j : 64+tx*4+(j-4));
                if(acc[i][j] > bestv[i]){ bestv[i]=acc[i][j]; besti[i]=cidx; }
            }
    }
    #pragma unroll
    for(int off=1; off<16; off<<=1)
        #pragma unroll
        for(int i=0;i<8;i++){
            float ov = __shfl_xor_sync(~0u, bestv[i], off);
            int   oi = __shfl_xor_sync(~0u, besti[i], off);
            if(ov>bestv[i] || (ov==bestv[i] && oi<besti[i])){ bestv[i]=ov; besti[i]=oi; }
        }
    if(!tx)
        #pragma unroll
        for(int i=0;i<8;i++){
            int nl = (i<4)? ty*4+i : 64+ty*4+(i-4);
            int n = nt*128 + nl;
            int gdst = (lb*256+n)*3 + ms;
            g_pmaxv[gdst]=bestv[i]; g_pmaxi[gdst]=besti[i];
        }
}

// ---- combine 3 argmax candidates, gather aligned, build ctx map ----
__global__ void k_ctx(const float* __restrict__ prompt, float* __restrict__ out){
    int gid = blockIdx.x, lb = gid>>8, n = gid&255, tid = threadIdx.x;
    __shared__ float red[256];
    __shared__ int   smi;
    __shared__ float sinv;
    if(!tid){
        float v=-3.f; int mi=0;
        #pragma unroll
        for(int s=0;s<3;s++){
            float vv=g_pmaxv[gid*3+s]; int ii=g_pmaxi[gid*3+s];
            if(vv>v || (vv==v && ii<mi)){ v=vv; mi=ii; }
        }
        out[OFF_RES+gid] = 0.5f*(1.f-v);
        out[OFF_IDX+gid] = (float)mi;
        smi = mi;
    }
    __syncthreads();
    const float* pr = prompt + (size_t)lb*2048*768 + (size_t)smi*768;
    float vloc[3]; float ss=0.f;
    #pragma unroll
    for(int i=0;i<3;i++){ float x=pr[tid+i*256]; vloc[i]=x; ss+=x*x; }
    red[tid]=ss; __syncthreads();
    for(int s=128;s;s>>=1){ if(tid<s) red[tid]+=red[tid+s]; __syncthreads(); }
    if(!tid) sinv = 1.f/fmaxf(sqrtf(red[0]),1e-12f);
    __syncthreads();
    float ainv = sinv;
    #pragma unroll
    for(int i=0;i<3;i++){
        int d = tid + i*256;
        float qv = g_qn[(size_t)gid*768 + d];
        float an = vloc[i]*ainv;
        g_cmap[((size_t)lb*768+d)*256 + n] = qv + fabsf(qv - an);
        out[OFF_ALN + (size_t)gid*768 + d] = vloc[i];
    }
}

// ---- generic training-mode BatchNorm2d ----
__global__ void k_bn(int which, const float* __restrict__ gg, const float* __restrict__ bb,
                     int C, int HW, int relu){
    float* x = which==0 ? g_cmap : which==1 ? g_x1 : g_x3;
    int l = blockIdx.x / C, c = blockIdx.x % C, tid = threadIdx.x;
    int per = HW >> 8;
    double s=0.0, s2=0.0;
    for(int b=0;b<16;b++)
        for(int i=0;i<per;i++){
            float v = x[(((size_t)(l*16+b))*C + c)*HW + i*256 + tid];
            s += v; s2 += (double)v*v;
        }
    __shared__ double rs[256], rs2[256];
    rs[tid]=s; rs2[tid]=s2; __syncthreads();
    for(int st=128;st;st>>=1){ if(tid<st){rs[tid]+=rs[tid+st]; rs2[tid]+=rs2[tid+st];} __syncthreads(); }
    __shared__ float sc, sh;
    if(!tid){
        double cnt = 16.0*HW, m = rs[0]/cnt, var = rs2[0]/cnt - m*m;
        float scale = gg[l*C+c]*rsqrtf((float)var + 1e-5f);
        sc = scale; sh = bb[l*C+c] - (float)m*scale;
    }
    __syncthreads();
    for(int b=0;b<16;b++)
        for(int i=0;i<per;i++){
            size_t a = (((size_t)(l*16+b))*C + c)*HW + i*256 + tid;
            float v = x[a]*sc + sh;
            x[a] = relu ? fmaxf(v,0.f) : v;
        }
}

// ---- GAP / GMP over post-BN cmap ----
__global__ void k_gapmax(){
    int lb = blockIdx.x/96, dc = blockIdx.x%96;
    int w = threadIdx.x>>5, lane = threadIdx.x&31;
    int d = dc*8 + w;
    const float* p = g_cmap + ((size_t)lb*768+d)*256;
    float s=0.f, mx=-3.4e38f;
    #pragma unroll
    for(int i=0;i<8;i++){ float x=p[lane+i*32]; s+=x; mx=fmaxf(mx,x); }
    #pragma unroll
    for(int o=16;o;o>>=1){ s += __shfl_xor_sync(~0u,s,o); mx = fmaxf(mx,__shfl_xor_sync(~0u,mx,o)); }
    if(!lane){ g_gap[lb*768+d]=s*(1.f/256.f); g_gmp[lb*768+d]=mx; }
}

// ---- conv1 3x3 768->128 @16x16, 128oc x 128pix tiles, K-split 3. grid 288 ----
__global__ __launch_bounds__(256,2) void k_conv1(){
    int bid = blockIdx.x;
    int ks = bid%3, pt = (bid/3)&1, lb = bid/6, l = lb>>4;
    int tid = threadIdx.x, tx = tid&15, ty = tid>>4;
    __shared__ float sA[16][132];
    __shared__ float sB[16][132];
    const float* W = g_w1t + (size_t)l*6912*128;
    const float* X = g_cmap + (size_t)lb*768*256;
    int p0 = pt*128;
    float acc[8][8];
    #pragma unroll
    for(int i=0;i<8;i++)
        #pragma unroll
        for(int j=0;j<8;j++) acc[i][j]=0.f;
    for(int kc=ks*144; kc<ks*144+144; kc++){
        int rs = kc/48, c0 = (kc%48)*16;
        int r = rs/3-1, s = rs%3-1;
        #pragma unroll
        for(int qq=0;qq<2;qq++){
            int e = tid + qq*256, o4 = e&31, k = e>>5;
            *(float4*)&sA[k][o4*4] = *(const float4*)(W + ((size_t)(kc*16+k))*128 + o4*4);
        }
        #pragma unroll
        for(int qq=0;qq<8;qq++){
            int e = tid + qq*256, k = e>>7, p = e&127;
            int pg = p0+p, y = (pg>>4)+r, x = (pg&15)+s;
            float v = 0.f;
            if((unsigned)y<16u && (unsigned)x<16u) v = X[((size_t)(c0+k))*256 + y*16 + x];
            sB[k][p] = v;
        }
        __syncthreads();
        #pragma unroll
        for(int k=0;k<16;k++){
            float4 av0 = *(const float4*)&sA[k][ty*4];
            float4 av1 = *(const float4*)&sA[k][64+ty*4];
            float4 bv0 = *(const float4*)&sB[k][tx*4];
            float4 bv1 = *(const float4*)&sB[k][64+tx*4];
            float av[8]={av0.x,av0.y,av0.z,av0.w,av1.x,av1.y,av1.z,av1.w};
            float bv[8]={bv0.x,bv0.y,bv0.z,bv0.w,bv1.x,bv1.y,bv1.z,bv1.w};
            #pragma unroll
            for(int i=0;i<8;i++)
                #pragma unroll
                for(int j=0;j<8;j++) acc[i][j]=fmaf(av[i],bv[j],acc[i][j]);
        }
        __syncthreads();
    }
    float* Y = (ks==0 ? g_x1 : ks==1 ? g_x1b : g_x1c) + (size_t)lb*128*256;
    #pragma unroll
    for(int i=0;i<8;i++){
        int o = (i<4)? ty*4+i : 64+ty*4+(i-4);
        #pragma unroll
        for(int j=0;j<8;j++){
            int pix = p0 + ((j<4)? tx*4+j : 64+tx*4+(j-4));
            Y[(size_t)o*256 + pix] = acc[i][j];
        }
    }
}

// ---- sum the 3 conv1 partials ----
__global__ void k_sum3(){
    int i = blockIdx.x*256 + threadIdx.x;
    g_x1[i] += g_x1b[i] + g_x1c[i];
}

// ---- convT1 2x2 s2 128->128. grid 768 ----
__global__ __launch_bounds__(256) void k_convT1(const float* __restrict__ bt1){
    int bid = blockIdx.x, pt = bid&3, pq = (bid>>2)&3, lb = bid>>4, l = lb>>4;
    int p = pq>>1, qd = pq&1;
    int tid = threadIdx.x, tx = tid&15, ty = tid>>4;
    __shared__ float sA[16][132];
    __shared__ float sB[16][68];
    const float* W = g_wt1t + (size_t)(l*4+pq)*128*128;
    const float* X = g_x1 + (size_t)lb*128*256;
    int p0 = pt*64;
    float acc[8][4];
    #pragma unroll
    for(int i=0;i<8;i++)
        #pragma unroll
        for(int j=0;j<4;j++) acc[i][j]=0.f;
    for(int kc=0; kc<8; kc++){
        #pragma unroll
        for(int qq=0;qq<2;qq++){
            int e = tid + qq*256, o4 = e&31, k = e>>5;
            *(float4*)&sA[k][o4*4] = *(const float4*)(W + ((size_t)(kc*16+k))*128 + o4*4);
        }
        { int p4 = tid&15, k = tid>>4;
          *(float4*)&sB[k][p4*4] = *(const float4*)(X + ((size_t)(kc*16+k))*256 + p0 + p4*4); }
        __syncthreads();
        #pragma unroll
        for(int k=0;k<16;k++){
            float4 a0 = *(const float4*)&sA[k][ty*4];
            float4 a1 = *(const float4*)&sA[k][64+ty*4];
            float4 b  = *(const float4*)&sB[k][tx*4];
            float av[8]={a0.x,a0.y,a0.z,a0.w,a1.x,a1.y,a1.z,a1.w};
            float bv[4]={b.x,b.y,b.z,b.w};
            #pragma unroll
            for(int i=0;i<8;i++)
                #pragma unroll
                for(int j=0;j<4;j++) acc[i][j]=fmaf(av[i],bv[j],acc[i][j]);
        }
        __syncthreads();
    }
    float* Y = g_x2 + (size_t)lb*128*1024;
    #pragma unroll
    for(int i=0;i<8;i++){
        int o = (i<4)? ty*4+i : 64+ty*4+(i-4);
        float bias = bt1[l*128+o];
        #pragma unroll
        for(int j=0;j<4;j++){
            int hw = p0 + tx*4 + j, h = hw>>4, w = hw&15;
            Y[(size_t)o*1024 + (2*h+p)*32 + 2*w + qd] = acc[i][j] + bias;
        }
    }
}

// ---- conv2 3x3 128->64 @32x32, 64oc x 256pix tiles. grid 192 ----
__global__ __launch_bounds__(256,2) void k_conv2(){
    int bid = blockIdx.x, pt = bid&3, lb = bid>>2, l = lb>>4;
    int tid = threadIdx.x, t8 = tid&7, ty = tid>>3;
    __shared__ float sA[16][68];
    __shared__ float sB[16][260];
    const float* W = g_w2t + (size_t)l*1152*64;
    const float* X = g_x2 + (size_t)lb*128*1024;
    int p0 = pt*256;
    float acc[8][8];
    #pragma unroll
    for(int i=0;i<8;i++)
        #pragma unroll
        for(int j=0;j<8;j++) acc[i][j]=0.f;
    for(int kc=0; kc<72; kc++){
        int rs = kc>>3, c0 = (kc&7)*16;
        int r = rs/3-1, s = rs%3-1;
        { int o4 = tid&15, k = tid>>4;
          *(float4*)&sA[k][o4*4] = *(const float4*)(W + ((size_t)(kc*16+k))*64 + o4*4); }
        #pragma unroll
        for(int qq=0;qq<16;qq++){
            int e = tid + qq*256, k = e>>8, p = e&255;
            int pg = p0+p, y = (pg>>5)+r, x = (pg&31)+s;
            float v = 0.f;
            if((unsigned)y<32u && (unsigned)x<32u) v = X[((size_t)(c0+k))*1024 + y*32 + x];
            sB[k][p] = v;
        }
        __syncthreads();
        #pragma unroll
        for(int k=0;k<16;k++){
            float4 av0 = *(const float4*)&sA[k][t8*4];
            float4 av1 = *(const float4*)&sA[k][32+t8*4];
            float4 bv0 = *(const float4*)&sB[k][ty*4];
            float4 bv1 = *(const float4*)&sB[k][128+ty*4];
            float av[8]={av0.x,av0.y,av0.z,av0.w,av1.x,av1.y,av1.z,av1.w};
            float bv[8]={bv0.x,bv0.y,bv0.z,bv0.w,bv1.x,bv1.y,bv1.z,bv1.w};
            #pragma unroll
            for(int i=0;i<8;i++)
                #pragma unroll
                for(int j=0;j<8;j++) acc[i][j]=fmaf(av[i],bv[j],acc[i][j]);
        }
        __syncthreads();
    }
    float* Y = g_x3 + (size_t)lb*64*1024;
    #pragma unroll
    for(int i=0;i<8;i++){
        int o = (i<4)? t8*4+i : 32+t8*4+(i-4);
        #pragma unroll
        for(int j=0;j<8;j++){
            int pix = p0 + ((j<4)? ty*4+j : 128+ty*4+(j-4));
            Y[(size_t)o*1024 + pix] = acc[i][j];
        }
    }
}

// ---- convT2 2x2 s2 64->64. grid 1536 ----
__global__ __launch_bounds__(256) void k_convT2(const float* __restrict__ bt2){
    int bid = blockIdx.x, pt = bid&7, pq = (bid>>3)&3, lb = bid>>5, l = lb>>4;
    int p = pq>>1, qd = pq&1;
    int tid = threadIdx.x, tx = tid&15, ty = tid>>4;
    __shared__ float sA[16][68];
    __shared__ float sB[16][132];
    const float* W = g_wt2t + (size_t)(l*4+pq)*64*64;
    const float* X = g_x3 + (size_t)lb*64*1024;
    int p0 = pt*128;
    float acc[4][8];
    #pragma unroll
    for(int i=0;i<4;i++)
        #pragma unroll
        for(int j=0;j<8;j++) acc[i][j]=0.f;
    for(int kc=0; kc<4; kc++){
        { int o4 = tid&15, k = tid>>4;
          *(float4*)&sA[k][o4*4] = *(const float4*)(W + ((size_t)(kc*16+k))*64 + o4*4); }
        #pragma unroll
        for(int qq=0;qq<2;qq++){
            int e = tid + qq*256, p4 = e&31, k = e>>5;
            *(float4*)&sB[k][p4*4] = *(const float4*)(X + ((size_t)(kc*16+k))*1024 + p0 + p4*4);
        }
        __syncthreads();
        #pragma unroll
        for(int k=0;k<16;k++){
            float4 a  = *(const float4*)&sA[k][ty*4];
            float4 b0 = *(const float4*)&sB[k][tx*4];
            float4 b1 = *(const float4*)&sB[k][64+tx*4];
            float av[4]={a.x,a.y,a.z,a.w};
            float bv[8]={b0.x,b0.y,b0.z,b0.w,b1.x,b1.y,b1.z,b1.w};
            #pragma unroll
            for(int i=0;i<4;i++)
                #pragma unroll
                for(int j=0;j<8;j++) acc[i][j]=fmaf(av[i],bv[j],acc[i][j]);
        }
        __syncthreads();
    }
    float* Y = g_x4 + (size_t)lb*64*4096;
    #pragma unroll
    for(int i=0;i<4;i++){
        int o = ty*4+i;
        float bias = bt2[l*64+o];
        #pragma unroll
        for(int j=0;j<8;j++){
            int hw = p0 + ((j<4)? tx*4+j : 64+tx*4+(j-4));
            int h = hw>>5, w = hw&31;
            Y[(size_t)o*4096 + (2*h+p)*64 + 2*w + qd] = acc[i][j] + bias;
        }
    }
}

// ---- conv3 1x1 64->2 ----
__global__ void k_conv3(const float* __restrict__ lw3, const float* __restrict__ lb3){
    int lb = blockIdx.x, l = lb>>4, tid = threadIdx.x;
    __shared__ float w[2][64];
    if(tid<128) w[tid>>6][tid&63] = lw3[l*128 + tid];
    __syncthreads();
    float b0 = lb3[l*2], b1 = lb3[l*2+1];
    const float* X = g_x4 + (size_t)lb*64*4096;
    float* R = g_raw + (size_t)lb*2*4096;
    for(int i=0;i<16;i++){
        int pix = tid + i*256;
        float a0=b0, a1=b1;
        #pragma unroll 8
        for(int c=0;c<64;c++){
            float v = X[(size_t)c*4096 + pix];
            a0 = fmaf(v, w[0][c], a0); a1 = fmaf(v, w[1][c], a1);
        }
        R[pix]=a0; R[4096+pix]=a1;
    }
}

// ---- adaptive pool 64->16 + patch outputs ----
__global__ void k_pool(float* __restrict__ out){
    int lb = blockIdx.x, tid = threadIdx.x;
    int py = tid>>4, px = tid&15;
    const float* R = g_raw + (size_t)lb*2*4096;
    float s0=0.f, s1=0.f;
    #pragma unroll
    for(int dy=0;dy<4;dy++)
        #pragma unroll
        for(int dx=0;dx<4;dx++){
            int a = (py*4+dy)*64 + px*4+dx;
            s0 += R[a]; s1 += R[4096+a];
        }
    s0 *= 0.0625f; s1 *= 0.0625f;
    float d = s1 - s0;
    out[OFF_PLOG + lb*256 + tid] = d;
    out[OFF_SCORE + lb*256 + tid] = 1.f/(1.f + expf(-d));
}

// ---- bilinear resize 64->240 ----
__global__ void k_resize(float* __restrict__ out){
    int idx = blockIdx.x*256 + threadIdx.x;
    if(idx >= 3*16*2*240*240) return;
    int x = idx%240, y = (idx/240)%240, m = idx/57600;
    const float* R = g_raw + (size_t)m*4096;
    float sy = (y+0.5f)*(64.f/240.f) - 0.5f;
    float sx = (x+0.5f)*(64.f/240.f) - 0.5f;
    int y0 = (int)floorf(sy); float fy = sy - y0;
    int x0 = (int)floorf(sx); float fx = sx - x0;
    int ya = max(y0,0), yb = min(y0+1,63), xa = max(x0,0), xb = min(x0+1,63);
    float v = (1.f-fy)*((1.f-fx)*R[ya*64+xa] + fx*R[ya*64+xb])
            +      fy *((1.f-fx)*R[yb*64+xa] + fx*R[yb*64+xb]);
    out[OFF_LOCAL + idx] = v;
}

// ---- global head ----
__global__ void k_head(const float* __restrict__ pool_logits, const float* __restrict__ mw1,
                       const float* __restrict__ mlng, const float* __restrict__ mlnb,
                       const float* __restrict__ mw2, const float* __restrict__ mb2,
                       float* __restrict__ out){
    int lb = blockIdx.x, l = lb>>4, tid = threadIdx.x;
    float pl0 = pool_logits[l*2], pl1 = pool_logits[l*2+1];
    float mx = fmaxf(pl0,pl1);
    float e0 = expf(pl0-mx), e1 = expf(pl1-mx);
    float pw0 = e0/(e0+e1), pw1 = e1/(e0+e1);
    if((lb&15)==0 && tid<2) out[OFF_PW + l*2 + tid] = tid ? pw1 : pw0;
    const float* gp = g_gap + (size_t)lb*768;
    const float* gm = g_gmp + (size_t)lb*768;
    const float* W = mw1 + (size_t)(l*128+tid)*768;
    float acc = 0.f;
    for(int d=0; d<768; d++) acc = fmaf(pw0*gp[d] + pw1*gm[d], W[d], acc);
    __shared__ double rd[128];
    rd[tid] = acc; __syncthreads();
    for(int s=64;s;s>>=1){ if(tid<s) rd[tid]+=rd[tid+s]; __syncthreads(); }
    __shared__ float smean;
    if(!tid) smean = (float)(rd[0]/128.0);
    __syncthreads();
    float m = smean, dx = acc - m;
    rd[tid] = (double)dx*dx; __syncthreads();
    for(int s=64;s;s>>=1){ if(tid<s) rd[tid]+=rd[tid+s]; __syncthreads(); }
    __shared__ float svar;
    if(!tid) svar = (float)(rd[0]/128.0);
    __syncthreads();
    float h = fmaxf(mlng[l*128+tid]*dx*rsqrtf(svar+1e-5f) + mlnb[l*128+tid], 0.f);
    rd[tid] = (double)h*mw2[l*256+tid]; __syncthreads();
    for(int s=64;s;s>>=1){ if(tid<s) rd[tid]+=rd[tid+s]; __syncthreads(); }
    __shared__ float sl0;
    if(!tid) sl0 = (float)rd[0];
    __syncthreads();
    rd[tid] = (double)h*mw2[l*256+128+tid]; __syncthreads();
    for(int s=64;s;s>>=1){ if(tid<s) rd[tid]+=rd[tid+s]; __syncthreads(); }
    if(!tid){
        float l1v = (float)rd[0] + mb2[l*2+1];
        float l0v = sl0 + mb2[l*2];
        out[OFF_GLOG + lb] = l1v - l0v;
    }
}

extern "C" void kernel_launch(void* const* d_in, const int* in_sizes, int n_in,
                              void* d_out, int out_size){
    const float* query   = (const float*)d_in[0];
    const float* prompt  = (const float*)d_in[1];
    const float* sbg     = (const float*)d_in[2];
    const float* sbb     = (const float*)d_in[3];
    const float* lw1     = (const float*)d_in[4];
    const float* lbn1g   = (const float*)d_in[5];
    const float* lbn1b   = (const float*)d_in[6];
    const float* lwt1    = (const float*)d_in[7];
    const float* lbt1    = (const float*)d_in[8];
    const float* lw2     = (const float*)d_in[9];
    const float* lbn2g   = (const float*)d_in[10];
    const float* lbn2b   = (const float*)d_in[11];
    const float* lwt2    = (const float*)d_in[12];
    const float* lbt2    = (const float*)d_in[13];
    const float* lw3     = (const float*)d_in[14];
    const float* lb3     = (const float*)d_in[15];
    const float* plog    = (const float*)d_in[16];
    const float* mw1     = (const float*)d_in[17];
    const float* mlng    = (const float*)d_in[18];
    const float* mlnb    = (const float*)d_in[19];
    const float* mw2     = (const float*)d_in[20];
    const float* mb2     = (const float*)d_in[21];
    float* out = (float*)d_out;

    k_tw<<<12192,256>>>(lw1, lw2, lwt1, lwt2);
    k_norm_q<<<1536,256>>>(query);
    k_norm_p<<<12288,256>>>(prompt);
    k_sim<<<288,256>>>(prompt);
    k_ctx<<<12288,256>>>(prompt, out);
    k_bn<<<3*768,256>>>(0, sbg, sbb, 768, 256, 0);
    k_gapmax<<<4608,256>>>();
    k_conv1<<<288,256>>>();
    k_sum3<<<6144,256>>>();
    k_bn<<<3*128,256>>>(1, lbn1g, lbn1b, 128, 256, 1);
    k_convT1<<<768,256>>>(lbt1);
    k_conv2<<<192,256>>>();
    k_bn<<<3*64,256>>>(2, lbn2g, lbn2b, 64, 1024, 1);
    k_convT2<<<1536,256>>>(lbt2);
    k_conv3<<<48,256>>>(lw3, lb3);
    k_pool<<<48,256>>>(out);
    k_resize<<<21600,256>>>(out);
    k_head<<<48,128>>>(plog, mw1, mlng, mlnb, mw2, mb2, out);
}